// round 2
// baseline (speedup 1.0000x reference)
#include <cuda_runtime.h>

#define N_ELEMS 33554432
#define N4 (N_ELEMS / 4)          // 8388608 float4 work items
#define ITEMS_PER_THREAD 2
#define THREADS 256

__device__ __forceinline__ void ssvi_compute(
    float4 lm, float4 y, float rho, float eta, float gamma, float one_m_rho2,
    float4& o, float4& g1, float4& g2)
{
    #pragma unroll
    for (int c = 0; c < 4; ++c) {
        float lmv = (&lm.x)[c];
        float yv  = (&y.x)[c];

        // phi = eta / (y^gamma * (1+y)^(1-gamma))
        float ly  = __logf(yv);
        float l1y = __logf(1.0f + yv);
        float phi = eta * __expf(-(gamma * ly + (1.0f - gamma) * l1y));

        float pl  = phi * lmv;
        float arg = fmaf(pl, pl, fmaf(2.0f * rho, pl, 1.0f));
        float invS = rsqrtf(arg);
        float S    = arg * invS;
        float half_y = 0.5f * yv;

        (&o.x)[c]  = half_y * (1.0f + rho * pl + S);
        (&g1.x)[c] = half_y * phi * (rho + (pl + rho) * invS);
        float invS3 = invS * invS * invS;
        (&g2.x)[c] = half_y * phi * phi * one_m_rho2 * invS3;
    }
}

__global__ __launch_bounds__(THREADS) void ssvi_kernel(
    const float4* __restrict__ logm,
    const float4* __restrict__ yATM,
    const float* __restrict__ raw_rho,
    const float* __restrict__ raw_eta,
    const float* __restrict__ raw_gamma,
    float4* __restrict__ out)
{
    const int tid = blockIdx.x * (THREADS * ITEMS_PER_THREAD) + threadIdx.x;
    const int i0 = tid;
    const int i1 = tid + THREADS;

    // Front-batched streaming loads (MLP_p1 = 4)
    float4 lm0 = __ldcs(&logm[i0]);
    float4 y0  = __ldcs(&yATM[i0]);
    float4 lm1 = __ldcs(&logm[i1]);
    float4 y1  = __ldcs(&yATM[i1]);

    // Broadcast scalars (tiny, L2-resident)
    float rho   = tanhf(__ldg(&raw_rho[0]));
    float eta   = __expf(__ldg(&raw_eta[0]));
    float gamma = __expf(__ldg(&raw_gamma[0]));
    float one_m_rho2 = 1.0f - rho * rho;

    const float4 zero = make_float4(0.f, 0.f, 0.f, 0.f);

    float4 o0, g10, g20, o1, g11, g21;
    ssvi_compute(lm0, y0, rho, eta, gamma, one_m_rho2, o0, g10, g20);
    ssvi_compute(lm1, y1, rho, eta, gamma, one_m_rho2, o1, g11, g21);

    __stcs(&out[i0],          o0);
    __stcs(&out[i1],          o1);
    __stcs(&out[N4 + i0],     zero);
    __stcs(&out[N4 + i1],     zero);
    __stcs(&out[2 * N4 + i0], g10);
    __stcs(&out[2 * N4 + i1], g11);
    __stcs(&out[3 * N4 + i0], g20);
    __stcs(&out[3 * N4 + i1], g21);
}

extern "C" void kernel_launch(void* const* d_in, const int* in_sizes, int n_in,
                              void* d_out, int out_size)
{
    const float4* logm = (const float4*)d_in[0];
    const float4* yATM = (const float4*)d_in[1];
    const float* raw_rho   = (const float*)d_in[2];
    const float* raw_eta   = (const float*)d_in[3];
    const float* raw_gamma = (const float*)d_in[4];
    float4* out = (float4*)d_out;

    const int blocks = N4 / (THREADS * ITEMS_PER_THREAD);  // exact: 2^23 / 512 = 16384
    ssvi_kernel<<<blocks, THREADS>>>(logm, yATM, raw_rho, raw_eta, raw_gamma, out);
}